// round 14
// baseline (speedup 1.0000x reference)
#include <cuda_runtime.h>
#include <cuda_bf16.h>
#include <cstdint>
#include <math.h>

// PolarVoxelizer R14: R12 + early point loads (global-load latency overlapped
// with smem bin-table setup + barrier).
//   K1 k_zero_tma (primary, 148x128): cp.async.bulk zeros, PDL trigger at entry.
//   K2 k_voxel (secondary, 733x256, launch_bounds(256,5)): loads its 3 float4s
//      FIRST, then fills bin tables, computes 4 lin indices into registers,
//      cudaGridDependencySynchronize(), scatters 1.0f.

#define Z_DEPTH   100
#define HALF_FOV  1.134f
#define R_MIN_C   2.7f
#define R_MAX_C   165.0f
#define SLOPE_REJ 2.2f        // atan(2.2)=1.1441 > HALF_FOV + any fp slop
#define MAX_RB    512
#define MAX_AB    256
#define ZCHUNK    32768       // bytes per bulk copy (= smem buffer size)

// Exact searchsorted(side='left') given an approximate starting index.
__device__ __forceinline__ int lb_fixup(const float* __restrict__ a, int n, float v, int idx) {
    idx = min(max(idx, 0), n);
    while (idx > 0 && a[idx - 1] >= v) --idx;
    while (idx < n && a[idx] < v) ++idx;
    return idx;
}

__global__ __launch_bounds__(128) void k_zero_tma(char* __restrict__ out,
                                                  long long total_bytes)
{
#if __CUDA_ARCH__ >= 900
    cudaTriggerProgrammaticLaunchCompletion();   // let k_voxel co-schedule now
#endif
    __shared__ __align__(128) float4 buf[ZCHUNK / 16];   // 32 KB of zeros

    for (int i = threadIdx.x; i < ZCHUNK / 16; i += blockDim.x)
        buf[i] = make_float4(0.f, 0.f, 0.f, 0.f);
    __syncthreads();
    asm volatile("fence.proxy.async.shared::cta;" ::: "memory");

    if (threadIdx.x == 0) {
        unsigned int saddr;
        asm("{ .reg .u64 t; cvta.to.shared.u64 t, %1; cvt.u32.u64 %0, t; }"
            : "=r"(saddr) : "l"(buf));

        long long nfull = total_bytes / ZCHUNK;
        for (long long c = blockIdx.x; c < nfull; c += gridDim.x) {
            char* g = out + c * (long long)ZCHUNK;
            asm volatile(
                "cp.async.bulk.global.shared::cta.bulk_group [%0], [%1], %2;"
                :: "l"(g), "r"(saddr), "r"((unsigned)ZCHUNK) : "memory");
        }
        long long rem = total_bytes - nfull * ZCHUNK;
        if (blockIdx.x == 0 && rem >= 16) {
            char* g = out + nfull * (long long)ZCHUNK;
            asm volatile(
                "cp.async.bulk.global.shared::cta.bulk_group [%0], [%1], %2;"
                :: "l"(g), "r"(saddr), "r"((unsigned)(rem & ~15LL)) : "memory");
        }
        asm volatile("cp.async.bulk.commit_group;" ::: "memory");
        asm volatile("cp.async.bulk.wait_group 0;" ::: "memory");
    }
}

__global__ __launch_bounds__(256, 5) void k_voxel(
    const float4* __restrict__ lidars4,
    const float* __restrict__ r_bins,
    const float* __restrict__ angle_bins,
    float* __restrict__ out,
    int npts, int num_r, int num_a,
    unsigned long long div_magic,          // exact i/n_per_s via (i*magic)>>40
    float a0, float inv_astep,
    float log2_rmin, float inv_log2_1pd)
{
    const int c = blockIdx.x * blockDim.x + threadIdx.x;   // chunk of 4 points
    const int nchunks = (npts + 3) >> 2;

    // ---- issue point loads FIRST: latency overlaps smem setup + barrier ----
    float4 q0, q1, q2;
    bool have = (c < nchunks);
    if (have) {
        int v4 = c * 3;
        q0 = lidars4[v4 + 0];
        q1 = lidars4[v4 + 1];
        q2 = lidars4[v4 + 2];
    }

    __shared__ float s_r[MAX_RB];
    __shared__ float s_a[MAX_AB];
    for (int i = threadIdx.x; i < num_r; i += blockDim.x) s_r[i] = r_bins[i];
    for (int i = threadIdx.x; i < num_a; i += blockDim.x) s_a[i] = angle_bins[i];
    __syncthreads();

    int lins[4] = {-1, -1, -1, -1};

    if (have) {
        int base = c * 4;
        float px[4] = {q0.x, q0.w, q1.z, q2.y};
        float py[4] = {q0.y, q1.x, q1.w, q2.z};
        float pz[4] = {q0.z, q1.y, q2.x, q2.w};

        #pragma unroll
        for (int k = 0; k < 4; ++k) {
            int i = base + k;
            float x = px[k], y = py[k], z = pz[k];

            // geometric pre-rejection: provably outside FOV (|angle| > 1.1441)
            if (i < npts && x > 0.0f && fabsf(y) <= SLOPE_REJ * x) {
                // radius: bit-exact vs XLA f32 (no FMA contraction, IEEE sqrt)
                float radius = __fsqrt_rn(__fadd_rn(__fmul_rn(x, x), __fmul_rn(y, y)));
                if ((radius < R_MAX_C) && (radius > R_MIN_C)) {
                    // angle: atan2f fast path, double refine near decision boundaries
                    float v = atan2f(y, x);
                    float eps = fmaxf(fabsf(v) * 1.0e-6f, 1.0e-7f);

                    int yg0 = (int)floorf((v - a0) * inv_astep);
                    int yg = lb_fixup(s_a, num_a, v, yg0);

                    bool near = (fabsf(fabsf(v) - HALF_FOV) <= eps);
                    if (yg < num_a && fabsf(v - s_a[yg])     <= eps) near = true;
                    if (yg > 0     && fabsf(v - s_a[yg - 1]) <= eps) near = true;
                    if (near) {
                        v = (float)atan2((double)y, (double)x);
                        yg = lb_fixup(s_a, num_a, v, yg);
                    }
                    if (fabsf(v) < HALF_FOV) {
                        int xg0 = (int)floorf((__log2f(radius) - log2_rmin) * inv_log2_1pd);
                        int xg = lb_fixup(s_r, num_r, radius, xg0);
                        int zg = (int)floorf(__fdiv_rn(__fsub_rn(z, -2.0f), 0.2f));
                        int s = (int)(((unsigned long long)i * div_magic) >> 40);
                        lins[k] = ((s * Z_DEPTH + zg) * num_a + yg) * num_r + xg;
                    }
                }
            }
        }
    }

#if __CUDA_ARCH__ >= 900
    cudaGridDependencySynchronize();   // wait for k_zero_tma completion + visibility
#endif

    #pragma unroll
    for (int k = 0; k < 4; ++k)
        if (lins[k] >= 0) out[lins[k]] = 1.0f;
}

extern "C" void kernel_launch(void* const* d_in, const int* in_sizes, int n_in,
                              void* d_out, int out_size) {
    const float* lidars     = (const float*)d_in[0];
    const float* r_bins     = (const float*)d_in[1];
    const float* angle_bins = (const float*)d_in[2];
    float* out = (float*)d_out;

    const int B = 2;  // output keeps only batch 0
    int num_r = in_sizes[1];
    int num_a = in_sizes[2];
    int npts  = in_sizes[0] / (3 * B);
    int S     = out_size / (Z_DEPTH * num_a * num_r);
    int n_per_s = npts / S;

    // Analytic grid params (guesses only; exactness via lb_fixup)
    double fov = 2.268;
    float a0 = (float)(-fov / 2.0);
    float inv_astep = (float)((num_a - 1) / fov);
    double delta = pow((165.0 + 0.0001) / 2.7, 1.0 / (double)(num_r - 1)) - 1.0;
    float log2_rmin = (float)(log(2.7) / log(2.0));
    float inv_log2_1pd = (float)(log(2.0) / log(1.0 + delta));

    // Exact floor(i / n_per_s) for i < 2^20: magic = ceil(2^40 / n_per_s)
    unsigned long long div_magic =
        ((1ULL << 40) + (unsigned long long)n_per_s - 1ULL) / (unsigned long long)n_per_s;

    int sms = 148;
    cudaDeviceGetAttribute(&sms, cudaDevAttrMultiProcessorCount, 0);

    // --- K1 (primary): TMA zero of the output; triggers PDL at entry ---
    k_zero_tma<<<sms, 128>>>((char*)out, (long long)out_size * 4);

    // --- K2 (secondary, PDL): 1 chunk/thread, 5 blocks/SM, single wave ---
    {
        int nchunks = (npts + 3) / 4;
        int v_blocks = (nchunks + 255) / 256;
        cudaLaunchConfig_t cfg = {};
        cfg.gridDim = dim3(v_blocks, 1, 1);
        cfg.blockDim = dim3(256, 1, 1);
        cfg.dynamicSmemBytes = 0;
        cfg.stream = 0;
        cudaLaunchAttribute attr[1];
        attr[0].id = cudaLaunchAttributeProgrammaticStreamSerialization;
        attr[0].val.programmaticStreamSerializationAllowed = 1;
        cfg.attrs = attr;
        cfg.numAttrs = 1;
        cudaLaunchKernelEx(&cfg, k_voxel,
            (const float4*)lidars, r_bins, angle_bins, out,
            npts, num_r, num_a, div_magic,
            a0, inv_astep, log2_rmin, inv_log2_1pd);
    }
}

// round 15
// speedup vs baseline: 1.5009x; 1.5009x over previous
#include <cuda_runtime.h>
#include <cuda_bf16.h>
#include <cstdint>
#include <math.h>

// PolarVoxelizer R15: R12 + analytic (LDS-free) bin indexing on the hot path.
//   Angle bins are uniform, radius bins geometric: when the fractional index
//   is provably far from an integer boundary, ceil(frac) IS the exact
//   searchsorted result (margins cover atan2f/__log2f error + f32 bin wobble).
//   Near-boundary points (~1e-3) take the exact smem lb_fixup fallback.
//   K1 k_zero_tma (primary): cp.async.bulk zeros, PDL trigger at entry.
//   K2 k_voxel (secondary, PDL, 5 blocks/SM single wave): register-resident
//      scatter after cudaGridDependencySynchronize().

#define Z_DEPTH   100
#define HALF_FOV  1.134f
#define R_MIN_C   2.7f
#define R_MAX_C   165.0f
#define SLOPE_REJ 2.2f        // atan(2.2)=1.1441 > HALF_FOV + any fp slop
#define MAX_RB    512
#define MAX_AB    256
#define ZCHUNK    32768       // bytes per bulk copy (= smem buffer size)
#define A_MARGIN  5.0e-4f     // angle index-units guard band
#define R_MARGIN  2.0e-3f     // radius index-units guard band

// Exact searchsorted(side='left') given an approximate starting index.
__device__ __forceinline__ int lb_fixup(const float* __restrict__ a, int n, float v, int idx) {
    idx = min(max(idx, 0), n);
    while (idx > 0 && a[idx - 1] >= v) --idx;
    while (idx < n && a[idx] < v) ++idx;
    return idx;
}

__global__ __launch_bounds__(128) void k_zero_tma(char* __restrict__ out,
                                                  long long total_bytes)
{
#if __CUDA_ARCH__ >= 900
    cudaTriggerProgrammaticLaunchCompletion();   // let k_voxel co-schedule now
#endif
    __shared__ __align__(128) float4 buf[ZCHUNK / 16];   // 32 KB of zeros

    for (int i = threadIdx.x; i < ZCHUNK / 16; i += blockDim.x)
        buf[i] = make_float4(0.f, 0.f, 0.f, 0.f);
    __syncthreads();
    asm volatile("fence.proxy.async.shared::cta;" ::: "memory");

    if (threadIdx.x == 0) {
        unsigned int saddr;
        asm("{ .reg .u64 t; cvta.to.shared.u64 t, %1; cvt.u32.u64 %0, t; }"
            : "=r"(saddr) : "l"(buf));

        long long nfull = total_bytes / ZCHUNK;
        for (long long c = blockIdx.x; c < nfull; c += gridDim.x) {
            char* g = out + c * (long long)ZCHUNK;
            asm volatile(
                "cp.async.bulk.global.shared::cta.bulk_group [%0], [%1], %2;"
                :: "l"(g), "r"(saddr), "r"((unsigned)ZCHUNK) : "memory");
        }
        long long rem = total_bytes - nfull * ZCHUNK;
        if (blockIdx.x == 0 && rem >= 16) {
            char* g = out + nfull * (long long)ZCHUNK;
            asm volatile(
                "cp.async.bulk.global.shared::cta.bulk_group [%0], [%1], %2;"
                :: "l"(g), "r"(saddr), "r"((unsigned)(rem & ~15LL)) : "memory");
        }
        asm volatile("cp.async.bulk.commit_group;" ::: "memory");
        asm volatile("cp.async.bulk.wait_group 0;" ::: "memory");
    }
}

__global__ __launch_bounds__(256, 5) void k_voxel(
    const float4* __restrict__ lidars4,
    const float* __restrict__ r_bins,
    const float* __restrict__ angle_bins,
    float* __restrict__ out,
    int npts, int num_r, int num_a,
    unsigned long long div_magic,          // exact i/n_per_s via (i*magic)>>40
    float a0, float inv_astep,
    float log2_rmin, float inv_log2_1pd)
{
    __shared__ float s_r[MAX_RB];
    __shared__ float s_a[MAX_AB];
    for (int i = threadIdx.x; i < num_r; i += blockDim.x) s_r[i] = r_bins[i];
    for (int i = threadIdx.x; i < num_a; i += blockDim.x) s_a[i] = angle_bins[i];
    __syncthreads();

    const int c = blockIdx.x * blockDim.x + threadIdx.x;   // chunk of 4 points
    const int nchunks = (npts + 3) >> 2;

    int lins[4] = {-1, -1, -1, -1};

    if (c < nchunks) {
        int base = c * 4;
        int v4 = c * 3;
        float4 q0 = lidars4[v4 + 0];
        float4 q1 = lidars4[v4 + 1];
        float4 q2 = lidars4[v4 + 2];
        float px[4] = {q0.x, q0.w, q1.z, q2.y};
        float py[4] = {q0.y, q1.x, q1.w, q2.z};
        float pz[4] = {q0.z, q1.y, q2.x, q2.w};

        #pragma unroll
        for (int k = 0; k < 4; ++k) {
            int i = base + k;
            float x = px[k], y = py[k], z = pz[k];

            // geometric pre-rejection: provably outside FOV (|angle| > 1.1441)
            if (i < npts && x > 0.0f && fabsf(y) <= SLOPE_REJ * x) {
                // radius: bit-exact vs XLA f32 (no FMA contraction, IEEE sqrt)
                float radius = __fsqrt_rn(__fadd_rn(__fmul_rn(x, x), __fmul_rn(y, y)));
                if ((radius < R_MAX_C) && (radius > R_MIN_C)) {
                    // ---- angle: analytic index, exact fallback near boundaries ----
                    float v = atan2f(y, x);
                    float frac = (v - a0) * inv_astep;
                    float rfrac = rintf(frac);
                    int yg;
                    bool okang;
                    if (fabsf(frac - rfrac) < A_MARGIN) {
                        // near a bin boundary (incl. FOV endpoints): exact path
                        float vf = (float)atan2((double)y, (double)x);
                        yg = lb_fixup(s_a, num_a, vf, (int)rfrac);
                        okang = fabsf(vf) < HALF_FOV;
                    } else {
                        yg = (int)ceilf(frac);   // provably exact searchsorted
                        okang = fabsf(v) < HALF_FOV;
                    }

                    if (okang) {
                        // ---- radius: analytic geometric index, rare fallback ----
                        float f = (__log2f(radius) - log2_rmin) * inv_log2_1pd;
                        float rf = rintf(f);
                        int xg;
                        if (fabsf(f - rf) < R_MARGIN) {
                            xg = lb_fixup(s_r, num_r, radius, (int)rf);
                        } else {
                            xg = (int)ceilf(f);  // provably exact searchsorted
                        }
                        int zg = (int)floorf(__fdiv_rn(__fsub_rn(z, -2.0f), 0.2f));
                        int s = (int)(((unsigned long long)i * div_magic) >> 40);
                        lins[k] = ((s * Z_DEPTH + zg) * num_a + yg) * num_r + xg;
                    }
                }
            }
        }
    }

#if __CUDA_ARCH__ >= 900
    cudaGridDependencySynchronize();   // wait for k_zero_tma completion + visibility
#endif

    #pragma unroll
    for (int k = 0; k < 4; ++k)
        if (lins[k] >= 0) out[lins[k]] = 1.0f;
}

extern "C" void kernel_launch(void* const* d_in, const int* in_sizes, int n_in,
                              void* d_out, int out_size) {
    const float* lidars     = (const float*)d_in[0];
    const float* r_bins     = (const float*)d_in[1];
    const float* angle_bins = (const float*)d_in[2];
    float* out = (float*)d_out;

    const int B = 2;  // output keeps only batch 0
    int num_r = in_sizes[1];
    int num_a = in_sizes[2];
    int npts  = in_sizes[0] / (3 * B);
    int S     = out_size / (Z_DEPTH * num_a * num_r);
    int n_per_s = npts / S;

    // Analytic grid params
    double fov = 2.268;
    float a0 = (float)(-fov / 2.0);
    float inv_astep = (float)((num_a - 1) / fov);
    double delta = pow((165.0 + 0.0001) / 2.7, 1.0 / (double)(num_r - 1)) - 1.0;
    float log2_rmin = (float)(log(2.7) / log(2.0));
    float inv_log2_1pd = (float)(log(2.0) / log(1.0 + delta));

    // Exact floor(i / n_per_s) for i < 2^20: magic = ceil(2^40 / n_per_s)
    unsigned long long div_magic =
        ((1ULL << 40) + (unsigned long long)n_per_s - 1ULL) / (unsigned long long)n_per_s;

    int sms = 148;
    cudaDeviceGetAttribute(&sms, cudaDevAttrMultiProcessorCount, 0);

    // --- K1 (primary): TMA zero of the output; triggers PDL at entry ---
    k_zero_tma<<<sms, 128>>>((char*)out, (long long)out_size * 4);

    // --- K2 (secondary, PDL): 1 chunk/thread, 5 blocks/SM, single wave ---
    {
        int nchunks = (npts + 3) / 4;
        int v_blocks = (nchunks + 255) / 256;
        cudaLaunchConfig_t cfg = {};
        cfg.gridDim = dim3(v_blocks, 1, 1);
        cfg.blockDim = dim3(256, 1, 1);
        cfg.dynamicSmemBytes = 0;
        cfg.stream = 0;
        cudaLaunchAttribute attr[1];
        attr[0].id = cudaLaunchAttributeProgrammaticStreamSerialization;
        attr[0].val.programmaticStreamSerializationAllowed = 1;
        cfg.attrs = attr;
        cfg.numAttrs = 1;
        cudaLaunchKernelEx(&cfg, k_voxel,
            (const float4*)lidars, r_bins, angle_bins, out,
            npts, num_r, num_a, div_magic,
            a0, inv_astep, log2_rmin, inv_log2_1pd);
    }
}